// round 10
// baseline (speedup 1.0000x reference)
#include <cuda_runtime.h>
#include <cuda_fp16.h>
#include <cstdint>

// LSTM N=64, T=512, D=1024, H=1024, G=4096.
// Phase A: xW = x @ Wx + b  -- HMMA fp16, Wx 2-term split, x fp16, 128x128 tiles.
// Phase B: persistent kernel, 128 CTAs x 512 threads, HMMA fp16 2-term split on Wh,
//          h single fp16 pre-fragmented; depth-4 B prefetch; pure-spin grid barrier.

#define N_  64
#define T_  512
#define D_  1024
#define H_  1024
#define G_  4096
#define M_  (N_ * T_)
#define NCTA 128
#define INV2048 (1.0f / 2048.0f)

typedef unsigned long long ull;

// -------- device globals --------
static __device__ __align__(16) float  g_xw[(size_t)M_ * G_];          // 512 MB
static __device__ __align__(16) __half g_xh[(size_t)M_ * D_];          // 64 MB  x fp16
static __device__ __align__(16) __half g_wxT[2ULL * G_ * D_];          // 16 MB  Wx^T split [term][col][k]
static __device__ __align__(16) __half g_whs[NCTA * 2 * 32 * 1024];    // 16 MB  split Wh^T
// h fragments: [phase][k16 0..63][np 0..3][lane 0..31][8 fp16]
static __device__ __align__(16) __half g_hf[2][64][4][32][8];
static __device__ unsigned g_count;

__device__ __forceinline__ float sigmoidf_(float x) { return 1.0f / (1.0f + __expf(-x)); }
__device__ __forceinline__ float fast_tanh(float x) {
    float ax = fabsf(x);
    float e = __expf(-2.0f * ax);
    float t = (1.0f - e) / (1.0f + e);
    return copysignf(t, x);
}

// -------- async copy --------
__device__ __forceinline__ void cp16(uint32_t s, const void* g) {
    asm volatile("cp.async.cg.shared.global [%0], [%1], 16;" :: "r"(s), "l"(g));
}
__device__ __forceinline__ void cp_commit() { asm volatile("cp.async.commit_group;"); }
template <int NN>
__device__ __forceinline__ void cp_wait() { asm volatile("cp.async.wait_group %0;" :: "n"(NN)); }

__device__ __forceinline__ uint32_t smem_u32(const void* p) {
    uint32_t a;
    asm("{ .reg .u64 t; cvta.to.shared.u64 t, %1; cvt.u32.u64 %0, t; }" : "=r"(a) : "l"(p));
    return a;
}

// -------- mma helpers --------
__device__ __forceinline__ void ldm4(uint32_t addr, uint32_t* r) {
    asm volatile("ldmatrix.sync.aligned.m8n8.x4.shared.b16 {%0,%1,%2,%3}, [%4];"
                 : "=r"(r[0]), "=r"(r[1]), "=r"(r[2]), "=r"(r[3]) : "r"(addr));
}
__device__ __forceinline__ void mma16816(float* d, const uint32_t* a, uint32_t b0, uint32_t b1) {
    asm volatile(
        "mma.sync.aligned.m16n8k16.row.col.f32.f16.f16.f32 "
        "{%0,%1,%2,%3}, {%4,%5,%6,%7}, {%8,%9}, {%0,%1,%2,%3};"
        : "+f"(d[0]), "+f"(d[1]), "+f"(d[2]), "+f"(d[3])
        : "r"(a[0]), "r"(a[1]), "r"(a[2]), "r"(a[3]), "r"(b0), "r"(b1));
}

// ---------------- prep kernels ----------------
__global__ void prep_x(const float* __restrict__ x) {
    size_t i = ((size_t)blockIdx.x * 256 + threadIdx.x) * 4;
    float4 v = *(const float4*)(x + i);
    __half h[4] = {__float2half_rn(v.x), __float2half_rn(v.y),
                   __float2half_rn(v.z), __float2half_rn(v.w)};
    *(uint2*)(g_xh + i) = *(uint2*)h;
}

__global__ void prep_wx(const float* __restrict__ Wx) {
    int k = blockIdx.x;                     // 0..1023
    const float* src = Wx + (size_t)k * G_;
    for (int col = threadIdx.x; col < G_; col += 256) {
        float w = src[col];
        __half hi = __float2half_rn(w);
        __half lo = __float2half_rn((w - __half2float(hi)) * 2048.0f);
        g_wxT[(size_t)col * D_ + k]        = hi;
        g_wxT[(size_t)(G_ + col) * D_ + k] = lo;
    }
}

__global__ void prep_wh(const float* __restrict__ Wh) {
    int b = blockIdx.x;
    int tid = threadIdx.x;
    int m = tid & 31;
    int g = m >> 3, j = m & 7;
    int col = g * 1024 + b * 8 + j;
    __half* dh = g_whs + ((size_t)(b * 2 + 0) * 32 + m) * 1024;
    __half* dl = g_whs + ((size_t)(b * 2 + 1) * 32 + m) * 1024;
    for (int k = tid >> 5; k < 1024; k += 8) {
        float w = Wh[(size_t)k * G_ + col];
        __half hi = __float2half_rn(w);
        __half lo = __float2half_rn((w - __half2float(hi)) * 2048.0f);
        dh[k] = hi;
        dl[k] = lo;
    }
}

__global__ void prep_h0(const float* __restrict__ h0) {
    int i = blockIdx.x * blockDim.x + threadIdx.x;
    if (i < N_ * H_) {
        int n = i >> 10, k = i & 1023;
        int lane = (n & 7) * 4 + ((k & 7) >> 1);
        int idx8 = ((n >> 3) & 1) * 4 + (((k >> 3) & 1) * 2 + (k & 1));
        g_hf[0][k >> 4][n >> 4][lane][idx8] = __float2half_rn(h0[i]);
    }
    if (i == 0) g_count = 0u;
}

// ---------------- Phase A: xW = x @ Wx + b via HMMA ----------------
// CTA tile M=128 x N=128, K in k32 chunks (32 iters), double-buffered, 512 thr.
// 16 warps: wm 0..3 (m32), wn 0..3 (n32). B kept [col][k] (proven pairing).
#define PA_PITCH 80                       // 32 halfs + 8 pad, bytes
#define PA_A(i)  ((i) * 10240)
#define PA_B(i)  (20480 + (i) * 20480)
#define PA_SMEM  61440

__global__ __launch_bounds__(512, 1)
void gemm_xw_hmma(const float* __restrict__ bias) {
    extern __shared__ char smem[];
    const uint32_t sb = smem_u32(smem);

    const int tid  = threadIdx.x;
    const int wid  = tid >> 5;
    const int lane = tid & 31;
    const int n0 = blockIdx.x * 128;
    const int m0 = blockIdx.y * 128;

    const char* Asrc = (const char*)g_xh + (size_t)m0 * 2048;   // + row*2048 + k*2
    const char* Bsrc = (const char*)g_wxT;                       // [term*4096+col][k]

    const int wm = wid & 3;
    const int wn = wid >> 2;

    auto issue = [&](int kt, int bi) {
        const int k0b = kt * 64;                // k32 -> 64 bytes
        const uint32_t ab = sb + PA_A(bi);
        const uint32_t bb = sb + PA_B(bi);
        {   // A: 512 pieces (128 rows x 64B)
            int row = tid >> 2, seg = tid & 3;
            cp16(ab + row * PA_PITCH + seg * 16,
                 Asrc + (size_t)row * 2048 + k0b + seg * 16);
        }
        #pragma unroll
        for (int i = 0; i < 2; i++) {           // B: 1024 pieces (256 rows x 64B)
            int p = tid + 512 * i;
            int row = p >> 2, seg = p & 3;
            int term = row >> 7, n = row & 127;
            cp16(bb + row * PA_PITCH + seg * 16,
                 Bsrc + ((size_t)(term * G_ + n0 + n)) * 2048 + k0b + seg * 16);
        }
    };

    float acc[2][2][4][4];                      // [term][mi][n8][4]
    #pragma unroll
    for (int s = 0; s < 2; s++)
        #pragma unroll
        for (int mi = 0; mi < 2; mi++)
            #pragma unroll
            for (int j = 0; j < 4; j++)
                #pragma unroll
                for (int i = 0; i < 4; i++) acc[s][mi][j][i] = 0.0f;

    const uint32_t lrow = (uint32_t)(lane & 15);
    const uint32_t lseg = (uint32_t)(lane >> 4) * 16;

    issue(0, 0);
    cp_commit();

    for (int kt = 0; kt < 32; kt++) {
        if (kt < 31) { issue(kt + 1, (kt + 1) & 1); cp_commit(); cp_wait<1>(); }
        else         { cp_wait<0>(); }
        __syncthreads();

        const uint32_t ab = sb + PA_A(kt & 1);
        const uint32_t bb = sb + PA_B(kt & 1);
        const uint32_t aAddr = ab + (wm * 32 + lrow) * PA_PITCH + lseg;

        #pragma unroll
        for (int k16 = 0; k16 < 2; k16++) {
            uint32_t af0[4], af1[4];
            ldm4(aAddr + k16 * 32, af0);
            ldm4(aAddr + 16 * PA_PITCH + k16 * 32, af1);
            #pragma unroll
            for (int s = 0; s < 2; s++) {
                #pragma unroll
                for (int tau = 0; tau < 2; tau++) {
                    uint32_t bf[4];
                    uint32_t baddr = bb + (s * 128 + wn * 32 + tau * 16 + lrow) * PA_PITCH
                                        + lseg + k16 * 32;
                    ldm4(baddr, bf);
                    // [col][k] non-trans: pairs (r0,r2), (r1,r3)
                    mma16816(acc[s][0][tau * 2 + 0], af0, bf[0], bf[2]);
                    mma16816(acc[s][0][tau * 2 + 1], af0, bf[1], bf[3]);
                    mma16816(acc[s][1][tau * 2 + 0], af1, bf[0], bf[2]);
                    mma16816(acc[s][1][tau * 2 + 1], af1, bf[1], bf[3]);
                }
            }
        }
        __syncthreads();
    }

    // epilogue: combine hi + lo/2048 + bias
    const int erow = lane >> 2;
    const int ecol = (lane & 3) * 2;
    #pragma unroll
    for (int mi = 0; mi < 2; mi++) {
        #pragma unroll
        for (int j = 0; j < 4; j++) {
            int col = n0 + wn * 32 + j * 8 + ecol;
            float2 bb2 = *(const float2*)(bias + col);
            int row = m0 + wm * 32 + mi * 16 + erow;
            float c0 = fmaf(acc[1][mi][j][0], INV2048, acc[0][mi][j][0]) + bb2.x;
            float c1 = fmaf(acc[1][mi][j][1], INV2048, acc[0][mi][j][1]) + bb2.y;
            float c2 = fmaf(acc[1][mi][j][2], INV2048, acc[0][mi][j][2]) + bb2.x;
            float c3 = fmaf(acc[1][mi][j][3], INV2048, acc[0][mi][j][3]) + bb2.y;
            *(float2*)(g_xw + (size_t)row * G_ + col)       = make_float2(c0, c1);
            *(float2*)(g_xw + (size_t)(row + 8) * G_ + col) = make_float2(c2, c3);
        }
    }
}

// ---------------- Phase B SMEM ----------------
#define WHS_PITCH 2064
#define SMP_OFF   132096
#define SMEM_TOT  (132096 + 33792)   // 165888

// 8 MMAs of one k16 step
#define PB_COMPUTE(A, B)                              \
    do {                                              \
        mma16816(dh[0][0], (A),      (B).x, (B).y);   \
        mma16816(dh[0][1], (A),      (B).z, (B).w);   \
        mma16816(dh[1][0], (A) + 4,  (B).x, (B).y);   \
        mma16816(dh[1][1], (A) + 4,  (B).z, (B).w);   \
        mma16816(dl[0][0], (A) + 8,  (B).x, (B).y);   \
        mma16816(dl[0][1], (A) + 8,  (B).z, (B).w);   \
        mma16816(dl[1][0], (A) + 12, (B).x, (B).y);   \
        mma16816(dl[1][1], (A) + 12, (B).z, (B).w);   \
    } while (0)

#define PB_LDA(kk, A)                                 \
    do {                                              \
        ldm4(aHi0 + (kk) * 32, (A));                  \
        ldm4(aHi1 + (kk) * 32, (A) + 4);              \
        ldm4(aLo0 + (kk) * 32, (A) + 8);              \
        ldm4(aLo1 + (kk) * 32, (A) + 12);             \
    } while (0)

__global__ __launch_bounds__(512, 1)
void lstm_mma(float* __restrict__ out) {
    extern __shared__ char smem[];
    const uint32_t sb = smem_u32(smem);
    float* sm_p = (float*)(smem + SMP_OFF);   // [4 wk][32 m][66 n]

    const int tid  = threadIdx.x;
    const int wid  = tid >> 5;
    const int lane = tid & 31;
    const int b    = blockIdx.x;

    // ---- one-time: Wh slice -> padded SMEM ----
    {
        const char* src = (const char*)(g_whs + (size_t)b * 2 * 32 * 1024);
        for (int p = tid; p < 8192; p += 512) {
            int row = p >> 7;
            int seg = p & 127;
            cp16(sb + row * WHS_PITCH + seg * 16, src + row * 2048 + seg * 16);
        }
        cp_commit();
        cp_wait<0>();
        __syncthreads();
    }

    const int wk = wid & 3;
    const int wn = wid >> 2;          // 0..3
    const int kk0 = wk * 16;

    const uint32_t aBase = sb + (uint32_t)(lane & 15) * WHS_PITCH + (uint32_t)(lane >> 4) * 16;
    const uint32_t aHi0 = aBase;
    const uint32_t aHi1 = aBase + 16 * WHS_PITCH;
    const uint32_t aLo0 = aBase + 32 * WHS_PITCH;
    const uint32_t aLo1 = aBase + 48 * WHS_PITCH;

    const int prow = lane >> 2;
    const int pcol = (lane & 3) * 2;

    const int en = tid >> 3;
    const int ej = tid & 7;
    const int jg = b * 8 + ej;
    float cc = 0.0f;
    const int wlane = (en & 7) * 4 + ((jg & 7) >> 1);
    const int widx8 = ((en >> 3) & 1) * 4 + (((jg >> 3) & 1) * 2 + (jg & 1));
    __half* hwp = &g_hf[0][jg >> 4][en >> 4][wlane][widx8];
    const size_t hphase_stride = (size_t)64 * 4 * 32 * 8;

    for (int t = 0; t < T_; t++) {
        const int p = t & 1, q = p ^ 1;
        const uint4* bPtr = (const uint4*)&g_hf[p][0][0][0][0] + lane;

        float dh[2][2][4], dl[2][2][4];
        #pragma unroll
        for (int m = 0; m < 2; m++)
            #pragma unroll
            for (int j = 0; j < 2; j++)
                #pragma unroll
                for (int i = 0; i < 4; i++) { dh[m][j][i] = 0.0f; dl[m][j][i] = 0.0f; }

        // depth-4 B prefetch ring + depth-2 A
        uint4 b0, b1, b2, b3;
        uint32_t aA[16], aB[16];
        b0 = bPtr[((kk0 + 0) * 4 + wn) * 32];
        b1 = bPtr[((kk0 + 1) * 4 + wn) * 32];
        b2 = bPtr[((kk0 + 2) * 4 + wn) * 32];
        b3 = bPtr[((kk0 + 3) * 4 + wn) * 32];
        PB_LDA(kk0, aA);

        // xw pre-activations (independent; consumed in epilogue)
        float xw[4];
        {
            const float* xp = g_xw + ((size_t)en * T_ + t) * G_ + jg;
            #pragma unroll
            for (int g = 0; g < 4; g++) xw[g] = xp[g * 1024];
        }

        #pragma unroll
        for (int s = 0; s < 16; s += 2) {
            PB_LDA(kk0 + s + 1, aB);
            if ((s & 2) == 0) {
                PB_COMPUTE(aA, b0);
                if (s + 4 < 16) b0 = bPtr[((kk0 + s + 4) * 4 + wn) * 32];
            } else {
                PB_COMPUTE(aA, b2);
                if (s + 4 < 16) b2 = bPtr[((kk0 + s + 4) * 4 + wn) * 32];
            }
            if (s + 2 < 16) PB_LDA(kk0 + s + 2, aA);
            if ((s & 2) == 0) {
                PB_COMPUTE(aB, b1);
                if (s + 5 < 16) b1 = bPtr[((kk0 + s + 5) * 4 + wn) * 32];
            } else {
                PB_COMPUTE(aB, b3);
                if (s + 5 < 16) b3 = bPtr[((kk0 + s + 5) * 4 + wn) * 32];
            }
        }

        // ---- combine + store partials ----
        #pragma unroll
        for (int m = 0; m < 2; m++) {
            #pragma unroll
            for (int j = 0; j < 2; j++) {
                float f0 = fmaf(dl[m][j][0], INV2048, dh[m][j][0]);
                float f1 = fmaf(dl[m][j][1], INV2048, dh[m][j][1]);
                float f2 = fmaf(dl[m][j][2], INV2048, dh[m][j][2]);
                float f3 = fmaf(dl[m][j][3], INV2048, dh[m][j][3]);
                float* qp = sm_p + (wk * 32 + m * 16 + prow) * 66 + wn * 16 + j * 8 + pcol;
                *(float2*)qp            = make_float2(f0, f1);
                *(float2*)(qp + 8 * 66) = make_float2(f2, f3);
            }
        }
        __syncthreads();

        // ---- gates + state update (h-fragment store first: critical path) ----
        {
            float a[4];
            #pragma unroll
            for (int g = 0; g < 4; g++) {
                int row = g * 8 + ej;
                float s0 = sm_p[(0 * 32 + row) * 66 + en] + sm_p[(1 * 32 + row) * 66 + en];
                float s1 = sm_p[(2 * 32 + row) * 66 + en] + sm_p[(3 * 32 + row) * 66 + en];
                a[g] = s0 + s1 + xw[g];
            }
            float ig = sigmoidf_(a[0]), fg = sigmoidf_(a[1]), og = sigmoidf_(a[2]);
            float gg = fast_tanh(a[3]);
            cc = fg * cc + ig * gg;
            float h = og * fast_tanh(cc);
            hwp[(size_t)q * hphase_stride] = __float2half_rn(h);
            out[((size_t)en * T_ + t) * H_ + jg] = h;
        }

        // ---- grid barrier (pure spin) ----
        __syncthreads();
        if (tid == 0) {
            asm volatile("red.release.gpu.global.add.u32 [%0], 1;" :: "l"(&g_count) : "memory");
            unsigned want = (unsigned)(t + 1) * NCTA;
            unsigned v;
            do {
                asm volatile("ld.acquire.gpu.global.u32 %0, [%1];" : "=r"(v) : "l"(&g_count) : "memory");
            } while (v < want);
        }
        __syncthreads();
    }
}

// ---------------- launch ----------------
extern "C" void kernel_launch(void* const* d_in, const int* in_sizes, int n_in,
                              void* d_out, int out_size) {
    const float* x  = (const float*)d_in[0];   // (N, T, D)
    const float* h0 = (const float*)d_in[1];   // (N, H)
    const float* Wx = (const float*)d_in[2];   // (D, 4H)
    const float* Wh = (const float*)d_in[3];   // (H, 4H)
    const float* b  = (const float*)d_in[4];   // (4H,)
    float* out = (float*)d_out;                // (N, T, H)

    prep_x<<<(int)((size_t)M_ * D_ / 1024), 256>>>(x);
    prep_wx<<<D_, 256>>>(Wx);
    prep_wh<<<NCTA, 256>>>(Wh);
    prep_h0<<<(N_ * H_ + 255) / 256, 256>>>(h0);

    cudaFuncSetAttribute(gemm_xw_hmma, cudaFuncAttributeMaxDynamicSharedMemorySize, PA_SMEM);
    dim3 gridA(G_ / 128, M_ / 128);
    gemm_xw_hmma<<<gridA, 512, PA_SMEM>>>(b);

    cudaFuncSetAttribute(lstm_mma, cudaFuncAttributeMaxDynamicSharedMemorySize, SMEM_TOT);
    lstm_mma<<<NCTA, 512, SMEM_TOT>>>(out);
}

// round 11
// speedup vs baseline: 1.0942x; 1.0942x over previous
#include <cuda_runtime.h>
#include <cuda_fp16.h>
#include <cstdint>

// LSTM N=64, T=512, D=1024, H=1024, G=4096.
// Phase A: xW = x @ Wx + b  -- HMMA fp16, Wx 2-term split, x fp16 (R9-proven 128x64).
// Phase B: persistent kernel, 128 CTAs x 512 threads, HMMA fp16 2-term split on Wh,
//          h single fp16 pre-fragmented. R11: warp tiling 8wk x 2wn(n32) halves
//          A-fragment LDSM crossbar traffic (512->256 KB/step) at equal B traffic.

#define N_  64
#define T_  512
#define D_  1024
#define H_  1024
#define G_  4096
#define M_  (N_ * T_)
#define NCTA 128
#define INV2048 (1.0f / 2048.0f)

typedef unsigned long long ull;

// -------- device globals --------
static __device__ __align__(16) float  g_xw[(size_t)M_ * G_];          // 512 MB
static __device__ __align__(16) __half g_xh[(size_t)M_ * D_];          // 64 MB
static __device__ __align__(16) __half g_wxT[2ULL * G_ * D_];          // 16 MB
static __device__ __align__(16) __half g_whs[NCTA * 2 * 32 * 1024];    // 16 MB
// h fragments: [phase][k16 0..63][np 0..3][lane 0..31][8 fp16]
static __device__ __align__(16) __half g_hf[2][64][4][32][8];
static __device__ unsigned g_count;

__device__ __forceinline__ float sigmoidf_(float x) { return 1.0f / (1.0f + __expf(-x)); }
__device__ __forceinline__ float fast_tanh(float x) {
    float ax = fabsf(x);
    float e = __expf(-2.0f * ax);
    float t = (1.0f - e) / (1.0f + e);
    return copysignf(t, x);
}

// -------- async copy --------
__device__ __forceinline__ void cp16(uint32_t s, const void* g) {
    asm volatile("cp.async.cg.shared.global [%0], [%1], 16;" :: "r"(s), "l"(g));
}
__device__ __forceinline__ void cp_commit() { asm volatile("cp.async.commit_group;"); }
template <int NN>
__device__ __forceinline__ void cp_wait() { asm volatile("cp.async.wait_group %0;" :: "n"(NN)); }

__device__ __forceinline__ uint32_t smem_u32(const void* p) {
    uint32_t a;
    asm("{ .reg .u64 t; cvta.to.shared.u64 t, %1; cvt.u32.u64 %0, t; }" : "=r"(a) : "l"(p));
    return a;
}

// -------- mma helpers --------
__device__ __forceinline__ void ldm4(uint32_t addr, uint32_t* r) {
    asm volatile("ldmatrix.sync.aligned.m8n8.x4.shared.b16 {%0,%1,%2,%3}, [%4];"
                 : "=r"(r[0]), "=r"(r[1]), "=r"(r[2]), "=r"(r[3]) : "r"(addr));
}
__device__ __forceinline__ void mma16816(float* d, const uint32_t* a, uint32_t b0, uint32_t b1) {
    asm volatile(
        "mma.sync.aligned.m16n8k16.row.col.f32.f16.f16.f32 "
        "{%0,%1,%2,%3}, {%4,%5,%6,%7}, {%8,%9}, {%0,%1,%2,%3};"
        : "+f"(d[0]), "+f"(d[1]), "+f"(d[2]), "+f"(d[3])
        : "r"(a[0]), "r"(a[1]), "r"(a[2]), "r"(a[3]), "r"(b0), "r"(b1));
}

// ---------------- prep kernels ----------------
__global__ void prep_x(const float* __restrict__ x) {
    size_t i = ((size_t)blockIdx.x * 256 + threadIdx.x) * 4;
    float4 v = *(const float4*)(x + i);
    __half h[4] = {__float2half_rn(v.x), __float2half_rn(v.y),
                   __float2half_rn(v.z), __float2half_rn(v.w)};
    *(uint2*)(g_xh + i) = *(uint2*)h;
}

__global__ void prep_wx(const float* __restrict__ Wx) {
    int k = blockIdx.x;
    const float* src = Wx + (size_t)k * G_;
    for (int col = threadIdx.x; col < G_; col += 256) {
        float w = src[col];
        __half hi = __float2half_rn(w);
        __half lo = __float2half_rn((w - __half2float(hi)) * 2048.0f);
        g_wxT[(size_t)col * D_ + k]        = hi;
        g_wxT[(size_t)(G_ + col) * D_ + k] = lo;
    }
}

__global__ void prep_wh(const float* __restrict__ Wh) {
    int b = blockIdx.x;
    int tid = threadIdx.x;
    int m = tid & 31;
    int g = m >> 3, j = m & 7;
    int col = g * 1024 + b * 8 + j;
    __half* dh = g_whs + ((size_t)(b * 2 + 0) * 32 + m) * 1024;
    __half* dl = g_whs + ((size_t)(b * 2 + 1) * 32 + m) * 1024;
    for (int k = tid >> 5; k < 1024; k += 8) {
        float w = Wh[(size_t)k * G_ + col];
        __half hi = __float2half_rn(w);
        __half lo = __float2half_rn((w - __half2float(hi)) * 2048.0f);
        dh[k] = hi;
        dl[k] = lo;
    }
}

__global__ void prep_h0(const float* __restrict__ h0) {
    int i = blockIdx.x * blockDim.x + threadIdx.x;
    if (i < N_ * H_) {
        int n = i >> 10, k = i & 1023;
        int lane = (n & 7) * 4 + ((k & 7) >> 1);
        int idx8 = ((n >> 3) & 1) * 4 + (((k >> 3) & 1) * 2 + (k & 1));
        g_hf[0][k >> 4][n >> 4][lane][idx8] = __float2half_rn(h0[i]);
    }
    if (i == 0) g_count = 0u;
}

// ---------------- Phase A: xW = x @ Wx + b via HMMA (R9-proven) ----------------
#define PA_PITCH 144
#define PA_ABUF(i) ((i) * 18432)
#define PA_BBUF(i) (36864 + (i) * 18432)
#define PA_SMEM 73728

__global__ __launch_bounds__(256, 2)
void gemm_xw_hmma(const float* __restrict__ bias) {
    extern __shared__ char smem[];
    const uint32_t sb = smem_u32(smem);

    const int tid  = threadIdx.x;
    const int wid  = tid >> 5;
    const int lane = tid & 31;
    const int bx = blockIdx.x;
    const int by = blockIdx.y;
    const int m0 = by * 128;
    const int n0 = bx * 64;

    const char* Asrc = (const char*)g_xh + (size_t)m0 * 2048;
    const char* Bsrc = (const char*)g_wxT;

    const int wm = wid >> 1;
    const int wn = wid & 1;

    auto issue = [&](int kt, int bi) {
        const int k0b = kt * 128;
        const uint32_t ab = sb + PA_ABUF(bi);
        const uint32_t bb = sb + PA_BBUF(bi);
        #pragma unroll
        for (int i = 0; i < 4; i++) {
            int p = tid + 256 * i;
            int row = p >> 3, seg = p & 7;
            cp16(ab + row * PA_PITCH + seg * 16,
                 Asrc + (size_t)row * 2048 + k0b + seg * 16);
        }
        #pragma unroll
        for (int i = 0; i < 4; i++) {
            int p = tid + 256 * i;
            int row = p >> 3, seg = p & 7;
            int term = row >> 6, n = row & 63;
            cp16(bb + row * PA_PITCH + seg * 16,
                 Bsrc + ((size_t)term * G_ + n0 + n) * 2048 + k0b + seg * 16);
        }
    };

    float acc[2][2][4][4];
    #pragma unroll
    for (int s = 0; s < 2; s++)
        #pragma unroll
        for (int mi = 0; mi < 2; mi++)
            #pragma unroll
            for (int j = 0; j < 4; j++)
                #pragma unroll
                for (int i = 0; i < 4; i++) acc[s][mi][j][i] = 0.0f;

    const uint32_t lrow = (uint32_t)(lane & 15);
    const uint32_t lseg = (uint32_t)(lane >> 4) * 16;

    issue(0, 0);
    cp_commit();

    for (int kt = 0; kt < 16; kt++) {
        if (kt < 15) { issue(kt + 1, (kt + 1) & 1); cp_commit(); cp_wait<1>(); }
        else         { cp_wait<0>(); }
        __syncthreads();

        const uint32_t ab = sb + PA_ABUF(kt & 1);
        const uint32_t bb = sb + PA_BBUF(kt & 1);
        const uint32_t aA0 = ab + (wm * 32 + lrow) * PA_PITCH + lseg;
        const uint32_t aA1 = aA0 + 16 * PA_PITCH;

        #pragma unroll
        for (int k16 = 0; k16 < 4; k16++) {
            uint32_t af[2][4];
            ldm4(aA0 + k16 * 32, af[0]);
            ldm4(aA1 + k16 * 32, af[1]);
            #pragma unroll
            for (int s = 0; s < 2; s++) {
                #pragma unroll
                for (int tau = 0; tau < 2; tau++) {
                    uint32_t bf[4];
                    uint32_t baddr = bb + (s * 64 + wn * 32 + tau * 16 + lrow) * PA_PITCH
                                        + lseg + k16 * 32;
                    ldm4(baddr, bf);
                    mma16816(acc[s][0][tau * 2 + 0], af[0], bf[0], bf[2]);
                    mma16816(acc[s][0][tau * 2 + 1], af[0], bf[1], bf[3]);
                    mma16816(acc[s][1][tau * 2 + 0], af[1], bf[0], bf[2]);
                    mma16816(acc[s][1][tau * 2 + 1], af[1], bf[1], bf[3]);
                }
            }
        }
        __syncthreads();
    }

    const int erow = lane >> 2;
    const int ecol = (lane & 3) * 2;
    #pragma unroll
    for (int mi = 0; mi < 2; mi++) {
        #pragma unroll
        for (int j = 0; j < 4; j++) {
            int col = n0 + wn * 32 + j * 8 + ecol;
            float2 bb2 = *(const float2*)(bias + col);
            int row = m0 + wm * 32 + mi * 16 + erow;
            float c0 = fmaf(acc[1][mi][j][0], INV2048, acc[0][mi][j][0]) + bb2.x;
            float c1 = fmaf(acc[1][mi][j][1], INV2048, acc[0][mi][j][1]) + bb2.y;
            float c2 = fmaf(acc[1][mi][j][2], INV2048, acc[0][mi][j][2]) + bb2.x;
            float c3 = fmaf(acc[1][mi][j][3], INV2048, acc[0][mi][j][3]) + bb2.y;
            *(float2*)(g_xw + (size_t)row * G_ + col)       = make_float2(c0, c1);
            *(float2*)(g_xw + (size_t)(row + 8) * G_ + col) = make_float2(c2, c3);
        }
    }
}

// ---------------- Phase B SMEM ----------------
// Whs 132096 B + sm_p [8 wk][32 m][66 n] f32 = 67584 B
#define WHS_PITCH 2064
#define SMP_OFF   132096
#define SMEM_TOT  (132096 + 67584)   // 199680

__global__ __launch_bounds__(512, 1)
void lstm_mma(float* __restrict__ out) {
    extern __shared__ char smem[];
    const uint32_t sb = smem_u32(smem);
    float* sm_p = (float*)(smem + SMP_OFF);   // [8][32][66]

    const int tid  = threadIdx.x;
    const int wid  = tid >> 5;
    const int lane = tid & 31;
    const int b    = blockIdx.x;

    // ---- one-time: Wh slice -> padded SMEM ----
    {
        const char* src = (const char*)(g_whs + (size_t)b * 2 * 32 * 1024);
        for (int p = tid; p < 8192; p += 512) {
            int row = p >> 7;
            int seg = p & 127;
            cp16(sb + row * WHS_PITCH + seg * 16, src + row * 2048 + seg * 16);
        }
        cp_commit();
        cp_wait<0>();
        __syncthreads();
    }

    // warp tiling: wk (k 8-split, 8 k16 each) x wn (n32 half)
    const int wk = wid & 7;
    const int wn = wid >> 3;          // 0..1
    const int kk0 = wk * 8;
    const int np0 = wn * 2;

    const uint32_t aBase = sb + (uint32_t)(lane & 15) * WHS_PITCH + (uint32_t)(lane >> 4) * 16;
    const uint32_t aHi0 = aBase;
    const uint32_t aHi1 = aBase + 16 * WHS_PITCH;
    const uint32_t aLo0 = aBase + 32 * WHS_PITCH;
    const uint32_t aLo1 = aBase + 48 * WHS_PITCH;

    const int prow = lane >> 2;
    const int pcol = (lane & 3) * 2;

    const int en = tid >> 3;
    const int ej = tid & 7;
    const int jg = b * 8 + ej;
    float cc = 0.0f;
    const int wlane = (en & 7) * 4 + ((jg & 7) >> 1);
    const int widx8 = ((en >> 3) & 1) * 4 + (((jg >> 3) & 1) * 2 + (jg & 1));
    __half* hwp = &g_hf[0][jg >> 4][en >> 4][wlane][widx8];
    const size_t hphase_stride = (size_t)64 * 4 * 32 * 8;

    for (int t = 0; t < T_; t++) {
        const int p = t & 1, q = p ^ 1;
        const uint4* bPtr = (const uint4*)&g_hf[p][0][0][0][0] + lane;

        // acc: [m][n8 0..3][4], hi + lo
        float dh[2][4][4], dl[2][4][4];
        #pragma unroll
        for (int m = 0; m < 2; m++)
            #pragma unroll
            for (int j = 0; j < 4; j++)
                #pragma unroll
                for (int i = 0; i < 4; i++) { dh[m][j][i] = 0.0f; dl[m][j][i] = 0.0f; }

        // B double-buffered (2 uint4 per k16), A single-buffered (SMEM, multi-warp hidden)
        uint4 b0A, b1A, b0B, b1B;
        uint32_t aR[16];
        b0A = bPtr[((kk0 + 0) * 4 + np0) * 32];
        b1A = bPtr[((kk0 + 0) * 4 + np0 + 1) * 32];

        float xw[4];
        {
            const float* xp = g_xw + ((size_t)en * T_ + t) * G_ + jg;
            #pragma unroll
            for (int g = 0; g < 4; g++) xw[g] = xp[g * 1024];
        }

        #pragma unroll
        for (int s = 0; s < 8; s++) {
            const int kk = kk0 + s;
            if (s & 1) {
                if (s + 1 < 8) {
                    b0A = bPtr[((kk + 1) * 4 + np0) * 32];
                    b1A = bPtr[((kk + 1) * 4 + np0 + 1) * 32];
                }
            } else {
                if (s + 1 < 8) {
                    b0B = bPtr[((kk + 1) * 4 + np0) * 32];
                    b1B = bPtr[((kk + 1) * 4 + np0 + 1) * 32];
                }
            }
            ldm4(aHi0 + kk * 32, aR);
            ldm4(aHi1 + kk * 32, aR + 4);
            ldm4(aLo0 + kk * 32, aR + 8);
            ldm4(aLo1 + kk * 32, aR + 12);
            const uint4& c0 = (s & 1) ? b0B : b0A;
            const uint4& c1 = (s & 1) ? b1B : b1A;
            mma16816(dh[0][0], aR,      c0.x, c0.y);
            mma16816(dh[0][1], aR,      c0.z, c0.w);
            mma16816(dh[0][2], aR,      c1.x, c1.y);
            mma16816(dh[0][3], aR,      c1.z, c1.w);
            mma16816(dh[1][0], aR + 4,  c0.x, c0.y);
            mma16816(dh[1][1], aR + 4,  c0.z, c0.w);
            mma16816(dh[1][2], aR + 4,  c1.x, c1.y);
            mma16816(dh[1][3], aR + 4,  c1.z, c1.w);
            mma16816(dl[0][0], aR + 8,  c0.x, c0.y);
            mma16816(dl[0][1], aR + 8,  c0.z, c0.w);
            mma16816(dl[0][2], aR + 8,  c1.x, c1.y);
            mma16816(dl[0][3], aR + 8,  c1.z, c1.w);
            mma16816(dl[1][0], aR + 12, c0.x, c0.y);
            mma16816(dl[1][1], aR + 12, c0.z, c0.w);
            mma16816(dl[1][2], aR + 12, c1.x, c1.y);
            mma16816(dl[1][3], aR + 12, c1.z, c1.w);
        }

        // ---- combine hi + lo/2048, store partials ----
        #pragma unroll
        for (int m = 0; m < 2; m++) {
            #pragma unroll
            for (int j = 0; j < 4; j++) {
                float f0 = fmaf(dl[m][j][0], INV2048, dh[m][j][0]);
                float f1 = fmaf(dl[m][j][1], INV2048, dh[m][j][1]);
                float f2 = fmaf(dl[m][j][2], INV2048, dh[m][j][2]);
                float f3 = fmaf(dl[m][j][3], INV2048, dh[m][j][3]);
                float* qp = sm_p + (wk * 32 + m * 16 + prow) * 66 + wn * 32 + j * 8 + pcol;
                *(float2*)qp            = make_float2(f0, f1);
                *(float2*)(qp + 8 * 66) = make_float2(f2, f3);
            }
        }
        __syncthreads();

        // ---- gates + state update (8-way partial reduction) ----
        {
            float a[4];
            #pragma unroll
            for (int g = 0; g < 4; g++) {
                int row = g * 8 + ej;
                float s0 = sm_p[(0 * 32 + row) * 66 + en] + sm_p[(1 * 32 + row) * 66 + en];
                float s1 = sm_p[(2 * 32 + row) * 66 + en] + sm_p[(3 * 32 + row) * 66 + en];
                float s2 = sm_p[(4 * 32 + row) * 66 + en] + sm_p[(5 * 32 + row) * 66 + en];
                float s3 = sm_p[(6 * 32 + row) * 66 + en] + sm_p[(7 * 32 + row) * 66 + en];
                a[g] = (s0 + s1) + (s2 + s3) + xw[g];
            }
            float ig = sigmoidf_(a[0]), fg = sigmoidf_(a[1]), og = sigmoidf_(a[2]);
            float gg = fast_tanh(a[3]);
            cc = fg * cc + ig * gg;
            float h = og * fast_tanh(cc);
            out[((size_t)en * T_ + t) * H_ + jg] = h;
            hwp[(size_t)q * hphase_stride] = __float2half_rn(h);
        }

        // ---- grid barrier (R9-proven) ----
        __syncthreads();
        if (tid == 0) {
            asm volatile("red.release.gpu.global.add.u32 [%0], 1;" :: "l"(&g_count) : "memory");
            unsigned want = (unsigned)(t + 1) * NCTA;
            unsigned v;
            asm volatile("ld.acquire.gpu.global.u32 %0, [%1];" : "=r"(v) : "l"(&g_count) : "memory");
            while (v < want) {
                __nanosleep(32);
                asm volatile("ld.acquire.gpu.global.u32 %0, [%1];" : "=r"(v) : "l"(&g_count) : "memory");
            }
        }
        __syncthreads();
    }
}

// ---------------- launch ----------------
extern "C" void kernel_launch(void* const* d_in, const int* in_sizes, int n_in,
                              void* d_out, int out_size) {
    const float* x  = (const float*)d_in[0];   // (N, T, D)
    const float* h0 = (const float*)d_in[1];   // (N, H)
    const float* Wx = (const float*)d_in[2];   // (D, 4H)
    const float* Wh = (const float*)d_in[3];   // (H, 4H)
    const float* b  = (const float*)d_in[4];   // (4H,)
    float* out = (float*)d_out;                // (N, T, H)

    prep_x<<<(int)((size_t)M_ * D_ / 1024), 256>>>(x);
    prep_wx<<<D_, 256>>>(Wx);
    prep_wh<<<NCTA, 256>>>(Wh);
    prep_h0<<<(N_ * H_ + 255) / 256, 256>>>(h0);

    cudaFuncSetAttribute(gemm_xw_hmma, cudaFuncAttributeMaxDynamicSharedMemorySize, PA_SMEM);
    dim3 gridA(G_ / 64, M_ / 128);
    gemm_xw_hmma<<<gridA, 256, PA_SMEM>>>(b);

    cudaFuncSetAttribute(lstm_mma, cudaFuncAttributeMaxDynamicSharedMemorySize, SMEM_TOT);
    lstm_mma<<<NCTA, 512, SMEM_TOT>>>(out);
}